// round 8
// baseline (speedup 1.0000x reference)
#include <cuda_runtime.h>
#include <cuda_fp16.h>

// Bilinear flow warp. input1: [B,C,H,W] fp32, flow: [B,2,H,W] fp32.
// Fixed shapes: B=8, C=64, H=256, W=448.
//
// Pass A (per batch): NCHW fp32 -> NHWC fp16 scratch.
// Pass B (per batch): 4-corner gather (corner = 64 contiguous fp16 ch = 128B),
//         batched LDGs for MLP, half2 FMA blend, fp16 smem tile, coalesced
//         NCHW fp32 writeback.
// The two passes are pipelined across the 8 batches on two streams:
// B(b) depends only on A(b), so B(b) overlaps A(b+1).

#define B_   8
#define C_   64
#define H_   256
#define W_   448
#define HW_  (H_ * W_)            // 114688
#define CHW_ (C_ * HW_)           // 7340032
#define TILES_PER_B (HW_ / 64)    // 1792 (W=448 divisible by 64: tile stays in one row)

// ~117 MB scratch: input in NHWC fp16 layout [B, H, W, C]
__device__ static __half g_nhwc[(size_t)B_ * HW_ * C_];

// ---------------------------------------------------------------------------
// Kernel A: NCHW fp32 -> NHWC fp16 for one batch. Tile = 64 ch x 64 px.
// ---------------------------------------------------------------------------
__global__ void __launch_bounds__(256) nchw_to_nhwc_f16(const float* __restrict__ in, int b)
{
    __shared__ float sm[64 * 65];    // [c][px], row stride 65

    int tile = blockIdx.x;
    int px0  = tile * 64;
    int tid  = threadIdx.x;

    // ---- load: float4 per thread (16 threads cover one channel row of 64 px) ----
    {
        int c_lo = tid >> 4;             // 0..15
        int px4  = (tid & 15) * 4;       // 0..60
        const float* src = in + b * CHW_ + px0 + px4;
        #pragma unroll
        for (int it = 0; it < 4; ++it) {
            int c = it * 16 + c_lo;
            float4 v = *(const float4*)(src + c * HW_);
            float* s = sm + c * 65 + px4;
            s[0] = v.x; s[1] = v.y; s[2] = v.z; s[3] = v.w;
        }
    }
    __syncthreads();

    // ---- store: 2048 half2 words (64 px x 32 words); 8 words per thread.
    //      Consecutive tid -> consecutive words: full 128B store wavefronts. ----
    {
        unsigned int* dst = (unsigned int*)(g_nhwc + (size_t)(b * HW_ + px0) * 64);
        #pragma unroll
        for (int k = 0; k < 8; ++k) {
            int idx = k * 256 + tid;
            int px  = idx >> 5;          // 0..63
            int cw  = idx & 31;          // channel word: channels 2cw, 2cw+1
            float a0 = sm[(2 * cw)     * 65 + px];
            float a1 = sm[(2 * cw + 1) * 65 + px];
            __half2 h = __floats2half2_rn(a0, a1);
            dst[px * 32 + cw] = *(unsigned int*)&h;
        }
    }
}

// ---------------------------------------------------------------------------
// Kernel B: gather from NHWC fp16, write NCHW fp32, one batch.
// Block = 256 threads handles 64 consecutive pixels (one row) x 64 channels.
// ---------------------------------------------------------------------------
__global__ void __launch_bounds__(256) warp_gather_f16(
    const float* __restrict__ flow,   // [B,2,H,W]
    float* __restrict__ out,          // [B,C,H,W]
    int b)
{
    __shared__ __half2 s_wh[64][4];   // per-pixel corner weights, pre-broadcast half2
    __shared__ int     s_o[64][4];    // per-pixel corner base offsets (half index)
    __shared__ __half2 s_r[64 * 33];  // result tile [px][c/2], stride 33 words

    int tile = blockIdx.x;
    int rem0 = tile * 64;
    int tid  = threadIdx.x;

    // ---- phase 1: one thread per (pixel, corner) ----
    {
        int px     = tid & 63;
        int corner = tid >> 6;           // 0:(y0,x0) 1:(y0,x1) 2:(y1,x0) 3:(y1,x1)
        int rem = rem0 + px;
        int h   = rem / W_;
        int w   = rem - h * W_;

        const float* fl = flow + b * 2 * HW_ + rem;
        float fx = __ldg(fl);
        float fy = __ldg(fl + HW_);

        float x = (float)w + fx;
        float y = (float)h + fy;

        float x0f = floorf(x);
        float y0f = floorf(y);

        int cx = corner & 1;
        int cy = corner >> 1;

        float wx1 = x - x0f;
        float wy1 = y - y0f;
        float wx = cx ? wx1 : (1.0f - wx1);
        float wy = cy ? wy1 : (1.0f - wy1);

        int xi = (int)x0f + cx;
        int yi = (int)y0f + cy;
        float valid = (xi >= 0 && xi < W_ && yi >= 0 && yi < H_) ? 1.0f : 0.0f;
        xi = min(max(xi, 0), W_ - 1);
        yi = min(max(yi, 0), H_ - 1);

        s_wh[px][corner] = __float2half2_rn(wx * wy * valid);
        s_o[px][corner]  = ((b * H_ + yi) * W_ + xi) * 64;
    }
    __syncthreads();

    // ---- phase 2: 8 warps x 8 pixels; lane covers channels (2*lane, 2*lane+1).
    //      Batched: 16 independent LDGs in flight per thread (4 px x 4 corners),
    //      then blend + conflict-free STS. ----
    {
        int wid  = tid >> 5;
        int lane = tid & 31;

        #pragma unroll
        for (int hblk = 0; hblk < 2; ++hblk) {
            int pbase = wid * 8 + hblk * 4;

            __half2 v[4][4];
            #pragma unroll
            for (int j = 0; j < 4; ++j) {
                int p = pbase + j;
                #pragma unroll
                for (int k = 0; k < 4; ++k)
                    v[j][k] = __ldg((const __half2*)(g_nhwc + s_o[p][k]) + lane);
            }

            #pragma unroll
            for (int j = 0; j < 4; ++j) {
                int p = pbase + j;
                __half2 r = __hfma2(v[j][0], s_wh[p][0],
                            __hfma2(v[j][1], s_wh[p][1],
                            __hfma2(v[j][2], s_wh[p][2],
                            __hmul2(v[j][3], s_wh[p][3]))));
                s_r[p * 33 + lane] = r;
            }
        }
    }
    __syncthreads();

    // ---- phase 3: coalesced NCHW fp32 writeback ----
    {
        int px   = tid & 63;
        int cgrp = tid >> 6;             // 0..3 -> channels 16*cgrp .. +15
        float* dst = out + b * CHW_ + rem0 + px;
        #pragma unroll
        for (int k = 0; k < 8; ++k) {
            __half2 hv = s_r[px * 33 + cgrp * 8 + k];
            float2 f = __half22float2(hv);
            int c = cgrp * 16 + 2 * k;
            dst[c * HW_]       = f.x;
            dst[(c + 1) * HW_] = f.y;
        }
    }
}

extern "C" void kernel_launch(void* const* d_in, const int* in_sizes, int n_in,
                              void* d_out, int out_size)
{
    const float* img  = (const float*)d_in[0];
    const float* flow = (const float*)d_in[1];
    float* out = (float*)d_out;

    // Two-stream pipeline across batches: A(b) on the origin stream,
    // B(b) on a side stream gated by an event -> B(b) overlaps A(b+1).
    // Stream/event creation is not a stream-ordered op (capture-safe, no
    // device memory). Called twice total (correctness + capture); the few
    // leaked handles are host-side only.
    cudaStream_t side;
    cudaStreamCreateWithFlags(&side, cudaStreamNonBlocking);

    for (int b = 0; b < B_; ++b) {
        nchw_to_nhwc_f16<<<TILES_PER_B, 256>>>(img, b);

        cudaEvent_t evA;
        cudaEventCreateWithFlags(&evA, cudaEventDisableTiming);
        cudaEventRecord(evA, 0);
        cudaStreamWaitEvent(side, evA, 0);

        warp_gather_f16<<<TILES_PER_B, 256, 0, side>>>(flow, out, b);
    }

    // Join: origin stream waits for the last gather so the captured graph's
    // leaf (and the harness's timing) covers all work.
    cudaEvent_t evDone;
    cudaEventCreateWithFlags(&evDone, cudaEventDisableTiming);
    cudaEventRecord(evDone, side);
    cudaStreamWaitEvent(0, evDone, 0);
}

// round 9
// speedup vs baseline: 1.0776x; 1.0776x over previous
#include <cuda_runtime.h>
#include <cuda_fp16.h>

// Bilinear flow warp. input1: [B,C,H,W] fp32, flow: [B,2,H,W] fp32.
// Fixed shapes: B=8, C=64, H=256, W=448.
//
// Pass A (4-batch chunk): NCHW fp32 -> NHWC fp16 scratch.
// Pass B (4-batch chunk): 4-corner gather (corner = 64 contiguous fp16 ch =
//         128B), batched LDGs for MLP, half2 FMA blend, fp16 smem tile,
//         coalesced NCHW fp32 writeback.
// Pipelined in 2 chunks: B(chunk0) overlaps A(chunk1). Chunk grids are
// ~6 occupancy waves, so per-kernel efficiency stays near monolithic.

#define B_   8
#define C_   64
#define H_   256
#define W_   448
#define HW_  (H_ * W_)            // 114688
#define CHW_ (C_ * HW_)           // 7340032
#define TILES_PER_B (HW_ / 64)    // 1792 (W=448 divisible by 64: tile stays in one row)
#define CHUNK_B 4                 // batches per pipeline chunk

// ~117 MB scratch: input in NHWC fp16 layout [B, H, W, C]
__device__ static __half g_nhwc[(size_t)B_ * HW_ * C_];

// ---------------------------------------------------------------------------
// Kernel A: NCHW fp32 -> NHWC fp16 for a chunk of batches. Tile = 64ch x 64px.
// ---------------------------------------------------------------------------
__global__ void __launch_bounds__(256) nchw_to_nhwc_f16(const float* __restrict__ in, int b0)
{
    __shared__ float sm[64 * 65];    // [c][px], row stride 65

    int blk  = blockIdx.x;
    int b    = b0 + blk / TILES_PER_B;
    int tile = blk % TILES_PER_B;
    int px0  = tile * 64;
    int tid  = threadIdx.x;

    // ---- load: float4 per thread (16 threads cover one channel row of 64 px) ----
    {
        int c_lo = tid >> 4;             // 0..15
        int px4  = (tid & 15) * 4;       // 0..60
        const float* src = in + b * CHW_ + px0 + px4;
        #pragma unroll
        for (int it = 0; it < 4; ++it) {
            int c = it * 16 + c_lo;
            float4 v = *(const float4*)(src + c * HW_);
            float* s = sm + c * 65 + px4;
            s[0] = v.x; s[1] = v.y; s[2] = v.z; s[3] = v.w;
        }
    }
    __syncthreads();

    // ---- store: 2048 half2 words (64 px x 32 words); 8 words per thread.
    //      Consecutive tid -> consecutive words: full 128B store wavefronts. ----
    {
        unsigned int* dst = (unsigned int*)(g_nhwc + (size_t)(b * HW_ + px0) * 64);
        #pragma unroll
        for (int k = 0; k < 8; ++k) {
            int idx = k * 256 + tid;
            int px  = idx >> 5;          // 0..63
            int cw  = idx & 31;          // channel word: channels 2cw, 2cw+1
            float a0 = sm[(2 * cw)     * 65 + px];
            float a1 = sm[(2 * cw + 1) * 65 + px];
            __half2 h = __floats2half2_rn(a0, a1);
            dst[px * 32 + cw] = *(unsigned int*)&h;
        }
    }
}

// ---------------------------------------------------------------------------
// Kernel B: gather from NHWC fp16, write NCHW fp32, chunk of batches.
// Block = 256 threads handles 64 consecutive pixels (one row) x 64 channels.
// ---------------------------------------------------------------------------
__global__ void __launch_bounds__(256) warp_gather_f16(
    const float* __restrict__ flow,   // [B,2,H,W]
    float* __restrict__ out,          // [B,C,H,W]
    int b0)
{
    __shared__ __half2 s_wh[64][4];   // per-pixel corner weights, pre-broadcast half2
    __shared__ int     s_o[64][4];    // per-pixel corner base offsets (half index)
    __shared__ __half2 s_r[64 * 33];  // result tile [px][c/2], stride 33 words

    int blk  = blockIdx.x;
    int b    = b0 + blk / TILES_PER_B;
    int tile = blk % TILES_PER_B;
    int rem0 = tile * 64;
    int tid  = threadIdx.x;

    // ---- phase 1: one thread per (pixel, corner) ----
    {
        int px     = tid & 63;
        int corner = tid >> 6;           // 0:(y0,x0) 1:(y0,x1) 2:(y1,x0) 3:(y1,x1)
        int rem = rem0 + px;
        int h   = rem / W_;
        int w   = rem - h * W_;

        const float* fl = flow + b * 2 * HW_ + rem;
        float fx = __ldg(fl);
        float fy = __ldg(fl + HW_);

        float x = (float)w + fx;
        float y = (float)h + fy;

        float x0f = floorf(x);
        float y0f = floorf(y);

        int cx = corner & 1;
        int cy = corner >> 1;

        float wx1 = x - x0f;
        float wy1 = y - y0f;
        float wx = cx ? wx1 : (1.0f - wx1);
        float wy = cy ? wy1 : (1.0f - wy1);

        int xi = (int)x0f + cx;
        int yi = (int)y0f + cy;
        float valid = (xi >= 0 && xi < W_ && yi >= 0 && yi < H_) ? 1.0f : 0.0f;
        xi = min(max(xi, 0), W_ - 1);
        yi = min(max(yi, 0), H_ - 1);

        s_wh[px][corner] = __float2half2_rn(wx * wy * valid);
        s_o[px][corner]  = ((b * H_ + yi) * W_ + xi) * 64;
    }
    __syncthreads();

    // ---- phase 2: 8 warps x 8 pixels; lane covers channels (2*lane, 2*lane+1).
    //      Batched: 16 independent LDGs in flight per thread (4 px x 4 corners),
    //      then blend + conflict-free STS. ----
    {
        int wid  = tid >> 5;
        int lane = tid & 31;

        #pragma unroll
        for (int hblk = 0; hblk < 2; ++hblk) {
            int pbase = wid * 8 + hblk * 4;

            __half2 v[4][4];
            #pragma unroll
            for (int j = 0; j < 4; ++j) {
                int p = pbase + j;
                #pragma unroll
                for (int k = 0; k < 4; ++k)
                    v[j][k] = __ldg((const __half2*)(g_nhwc + s_o[p][k]) + lane);
            }

            #pragma unroll
            for (int j = 0; j < 4; ++j) {
                int p = pbase + j;
                __half2 r = __hfma2(v[j][0], s_wh[p][0],
                            __hfma2(v[j][1], s_wh[p][1],
                            __hfma2(v[j][2], s_wh[p][2],
                            __hmul2(v[j][3], s_wh[p][3]))));
                s_r[p * 33 + lane] = r;
            }
        }
    }
    __syncthreads();

    // ---- phase 3: coalesced NCHW fp32 writeback ----
    {
        int px   = tid & 63;
        int cgrp = tid >> 6;             // 0..3 -> channels 16*cgrp .. +15
        float* dst = out + b * CHW_ + rem0 + px;
        #pragma unroll
        for (int k = 0; k < 8; ++k) {
            __half2 hv = s_r[px * 33 + cgrp * 8 + k];
            float2 f = __half22float2(hv);
            int c = cgrp * 16 + 2 * k;
            dst[c * HW_]       = f.x;
            dst[(c + 1) * HW_] = f.y;
        }
    }
}

extern "C" void kernel_launch(void* const* d_in, const int* in_sizes, int n_in,
                              void* d_out, int out_size)
{
    const float* img  = (const float*)d_in[0];
    const float* flow = (const float*)d_in[1];
    float* out = (float*)d_out;

    const int chunk_blocks = CHUNK_B * TILES_PER_B;   // 7168 (~6 waves)

    // Two-chunk pipeline: A(c0) -> [B(c0) on side || A(c1) on origin] -> B(c1).
    // Event/stream creation is host-side only (capture-safe, no device mem).
    cudaStream_t side;
    cudaStreamCreateWithFlags(&side, cudaStreamNonBlocking);

    // chunk 0: batches 0..3
    nchw_to_nhwc_f16<<<chunk_blocks, 256>>>(img, 0);
    cudaEvent_t evA0;
    cudaEventCreateWithFlags(&evA0, cudaEventDisableTiming);
    cudaEventRecord(evA0, 0);
    cudaStreamWaitEvent(side, evA0, 0);
    warp_gather_f16<<<chunk_blocks, 256, 0, side>>>(flow, out, 0);

    // chunk 1: batches 4..7 (A overlaps B(chunk0))
    nchw_to_nhwc_f16<<<chunk_blocks, 256>>>(img, CHUNK_B);
    cudaEvent_t evA1;
    cudaEventCreateWithFlags(&evA1, cudaEventDisableTiming);
    cudaEventRecord(evA1, 0);
    cudaStreamWaitEvent(side, evA1, 0);
    warp_gather_f16<<<chunk_blocks, 256, 0, side>>>(flow, out, CHUNK_B);

    // Join: origin stream waits for the last gather.
    cudaEvent_t evDone;
    cudaEventCreateWithFlags(&evDone, cudaEventDisableTiming);
    cudaEventRecord(evDone, side);
    cudaStreamWaitEvent(0, evDone, 0);
}

// round 10
// speedup vs baseline: 1.1254x; 1.0444x over previous
#include <cuda_runtime.h>
#include <cuda_fp16.h>

// Bilinear flow warp. input1: [B,C,H,W] fp32, flow: [B,2,H,W] fp32.
// Fixed shapes: B=8, C=64, H=256, W=448.
//
// Pass A: NCHW fp32 -> NHWC fp16 scratch (near-DRAM-bound already).
// Pass B: 4-corner gather (corner = 64 contiguous fp16 ch = 128B = 1 L1
//         wavefront/warp). MLP=8 per thread batched loads + forced 32-reg
//         budget for ~full occupancy. half2 FMA blend, fp16 smem tile,
//         coalesced NCHW fp32 writeback.
// Serial launches (stream pipelining measured as a loss on this pair).

#define B_   8
#define C_   64
#define H_   256
#define W_   448
#define HW_  (H_ * W_)            // 114688
#define CHW_ (C_ * HW_)           // 7340032
#define TILES_PER_B (HW_ / 64)    // 1792 (W=448 divisible by 64: tile stays in one row)

// ~117 MB scratch: input in NHWC fp16 layout [B, H, W, C]
__device__ static __half g_nhwc[(size_t)B_ * HW_ * C_];

// ---------------------------------------------------------------------------
// Kernel A: NCHW fp32 -> NHWC fp16.  Tile = 64 ch x 64 px, 256 threads.
// ---------------------------------------------------------------------------
__global__ void __launch_bounds__(256) nchw_to_nhwc_f16(const float* __restrict__ in)
{
    __shared__ float sm[64 * 65];    // [c][px], row stride 65

    int blk  = blockIdx.x;
    int b    = blk / TILES_PER_B;
    int tile = blk - b * TILES_PER_B;
    int px0  = tile * 64;
    int tid  = threadIdx.x;

    // ---- load: float4 per thread (16 threads cover one channel row of 64 px) ----
    {
        int c_lo = tid >> 4;             // 0..15
        int px4  = (tid & 15) * 4;       // 0..60
        const float* src = in + b * CHW_ + px0 + px4;
        #pragma unroll
        for (int it = 0; it < 4; ++it) {
            int c = it * 16 + c_lo;
            float4 v = *(const float4*)(src + c * HW_);
            float* s = sm + c * 65 + px4;
            s[0] = v.x; s[1] = v.y; s[2] = v.z; s[3] = v.w;
        }
    }
    __syncthreads();

    // ---- store: 2048 half2 words (64 px x 32 words); 8 words per thread.
    //      Consecutive tid -> consecutive words: full 128B store wavefronts. ----
    {
        unsigned int* dst = (unsigned int*)(g_nhwc + (size_t)(b * HW_ + px0) * 64);
        #pragma unroll
        for (int k = 0; k < 8; ++k) {
            int idx = k * 256 + tid;
            int px  = idx >> 5;          // 0..63
            int cw  = idx & 31;          // channel word: channels 2cw, 2cw+1
            float a0 = sm[(2 * cw)     * 65 + px];
            float a1 = sm[(2 * cw + 1) * 65 + px];
            __half2 h = __floats2half2_rn(a0, a1);
            dst[px * 32 + cw] = *(unsigned int*)&h;
        }
    }
}

// ---------------------------------------------------------------------------
// Kernel B: gather from NHWC fp16, write NCHW fp32.
// Block = 256 threads handles 64 consecutive pixels (one row) x 64 channels.
// __launch_bounds__(256, 8): cap regs at 32 -> ~full occupancy.
// ---------------------------------------------------------------------------
__global__ void __launch_bounds__(256, 8) warp_gather_f16(
    const float* __restrict__ flow,   // [B,2,H,W]
    float* __restrict__ out)          // [B,C,H,W]
{
    __shared__ __half2 s_wh[64][4];   // per-pixel corner weights, pre-broadcast half2
    __shared__ int     s_o[64][4];    // per-pixel corner base offsets (half index)
    __shared__ __half2 s_r[64 * 33];  // result tile [px][c/2], stride 33 words

    int blk  = blockIdx.x;
    int b    = blk / TILES_PER_B;
    int tile = blk - b * TILES_PER_B;
    int rem0 = tile * 64;
    int tid  = threadIdx.x;

    // ---- phase 1: one thread per (pixel, corner) ----
    {
        int px     = tid & 63;
        int corner = tid >> 6;           // 0:(y0,x0) 1:(y0,x1) 2:(y1,x0) 3:(y1,x1)
        int rem = rem0 + px;
        int h   = rem / W_;
        int w   = rem - h * W_;

        const float* fl = flow + b * 2 * HW_ + rem;
        float fx = __ldg(fl);
        float fy = __ldg(fl + HW_);

        float x = (float)w + fx;
        float y = (float)h + fy;

        float x0f = floorf(x);
        float y0f = floorf(y);

        int cx = corner & 1;
        int cy = corner >> 1;

        float wx1 = x - x0f;
        float wy1 = y - y0f;
        float wx = cx ? wx1 : (1.0f - wx1);
        float wy = cy ? wy1 : (1.0f - wy1);

        int xi = (int)x0f + cx;
        int yi = (int)y0f + cy;
        float valid = (xi >= 0 && xi < W_ && yi >= 0 && yi < H_) ? 1.0f : 0.0f;
        xi = min(max(xi, 0), W_ - 1);
        yi = min(max(yi, 0), H_ - 1);

        s_wh[px][corner] = __float2half2_rn(wx * wy * valid);
        s_o[px][corner]  = ((b * H_ + yi) * W_ + xi) * 64;
    }
    __syncthreads();

    // ---- phase 2: 8 warps x 8 pixels; lane covers channels (2*lane, 2*lane+1).
    //      MLP=8: 2 pixels x 4 corners of independent LDGs in flight,
    //      then blend + conflict-free STS. ----
    {
        int wid  = tid >> 5;
        int lane = tid & 31;

        #pragma unroll
        for (int hblk = 0; hblk < 4; ++hblk) {
            int pbase = wid * 8 + hblk * 2;

            __half2 v[2][4];
            #pragma unroll
            for (int j = 0; j < 2; ++j) {
                int p = pbase + j;
                #pragma unroll
                for (int k = 0; k < 4; ++k)
                    v[j][k] = __ldg((const __half2*)(g_nhwc + s_o[p][k]) + lane);
            }

            #pragma unroll
            for (int j = 0; j < 2; ++j) {
                int p = pbase + j;
                __half2 r = __hfma2(v[j][0], s_wh[p][0],
                            __hfma2(v[j][1], s_wh[p][1],
                            __hfma2(v[j][2], s_wh[p][2],
                            __hmul2(v[j][3], s_wh[p][3]))));
                s_r[p * 33 + lane] = r;
            }
        }
    }
    __syncthreads();

    // ---- phase 3: coalesced NCHW fp32 writeback ----
    {
        int px   = tid & 63;
        int cgrp = tid >> 6;             // 0..3 -> channels 16*cgrp .. +15
        float* dst = out + b * CHW_ + rem0 + px;
        #pragma unroll
        for (int k = 0; k < 8; ++k) {
            __half2 hv = s_r[px * 33 + cgrp * 8 + k];
            float2 f = __half22float2(hv);
            int c = cgrp * 16 + 2 * k;
            dst[c * HW_]       = f.x;
            dst[(c + 1) * HW_] = f.y;
        }
    }
}

extern "C" void kernel_launch(void* const* d_in, const int* in_sizes, int n_in,
                              void* d_out, int out_size)
{
    const float* img  = (const float*)d_in[0];
    const float* flow = (const float*)d_in[1];
    float* out = (float*)d_out;

    const int blocks = B_ * TILES_PER_B;   // 14336
    nchw_to_nhwc_f16<<<blocks, 256>>>(img);
    warp_gather_f16<<<blocks, 256>>>(flow, out);
}